// round 14
// baseline (speedup 1.0000x reference)
#include <cuda_runtime.h>
#include <cuda_fp16.h>

#define NUSERS  100000
#define NNODES  300000
#define NEDGES  1250000
#define HID     64
#define EIG     16
#define NPATHS  14
#define LN_EPS  1e-5f

#define SCAN_BLK 1024
#define NBLK1    ((NNODES + SCAN_BLK - 1) / SCAN_BLK)   // 293
#define NHALF    (NEDGES / 2)                            // 625000 (even)

// ---------------- scratch (device globals: no allocation allowed) ----------
__device__ float  g_yA[(size_t)NNODES * HID];    // f32 layernormed emb (L0)
__device__ float  g_yB[(size_t)NNODES * HID];    // f32 layernormed emb (L1)
__device__ __half g_hA[(size_t)NNODES * HID];    // fp16 copy for score (L0)
__device__ __half g_hB[(size_t)NNODES * HID];    // fp16 copy for score (L1)
__device__ __align__(16) int2  g_edge[NEDGES];   // {row, col|pt<<19} sorted by row
__device__ __align__(16) float g_yeig[NEDGES];   // dot(eig[r],eig[c]) per edge
__device__ __align__(16) float g_e0[NEDGES];     // exp(s0) per sorted edge
__device__ int    g_count[NNODES];               // row degree
__device__ int    g_off[NNODES];                 // CSR row offsets
__device__ int    g_cursor[NNODES];              // scatter cursors
__device__ int    g_total;                       // scan base allocator

// ---------------------------------------------------------------------------
__device__ __forceinline__ void store_h4(__half* hbase, int row, int lane, float4 v) {
    union { uint2 u; __half2 h[2]; } pk;
    pk.h[0] = __floats2half2_rn(v.x, v.y);
    pk.h[1] = __floats2half2_rn(v.z, v.w);
    ((uint2*)(hbase + (size_t)row * HID))[lane] = pk.u;
}

__device__ __forceinline__ float hdot8(uint2 ur, uint2 uc) {
    float2 a = __half22float2(*(const __half2*)&ur.x);
    float2 b = __half22float2(*(const __half2*)&uc.x);
    float p = a.x * b.x + a.y * b.y;
    a = __half22float2(*(const __half2*)&ur.y);
    b = __half22float2(*(const __half2*)&uc.y);
    return p + a.x * b.x + a.y * b.y;
}

// ---------------------------------------------------------------------------
// Layer-0 layernorm: half-warp per row, float4 lanes. Runs FIRST; also zeroes
// the CSR histogram.  g_yA/g_hA = LN(concat(ue,ie)); out = concat(ue,ie)
__global__ void __launch_bounds__(256) k_ln0(const float* __restrict__ ue,
                                             const float* __restrict__ ie,
                                             float* __restrict__ out) {
    int tid  = blockIdx.x * blockDim.x + threadIdx.x;
    int row  = tid >> 4;
    int lane = threadIdx.x & 15;
    if (row >= NNODES) return;

    if (lane == 0) g_count[row] = 0;
    if (tid == 0)  g_total = 0;

    const float* src = (row < NUSERS)
        ? ue + (size_t)row * HID
        : ie + (size_t)(row - NUSERS) * HID;
    float4 v = ((const float4*)src)[lane];

    float s  = v.x + v.y + v.z + v.w;
    float sq = v.x * v.x + v.y * v.y + v.z * v.z + v.w * v.w;
    #pragma unroll
    for (int o = 8; o; o >>= 1) {
        s  += __shfl_xor_sync(0xFFFFFFFFu, s,  o);
        sq += __shfl_xor_sync(0xFFFFFFFFu, sq, o);
    }
    float mu  = s * (1.0f / HID);
    float var = sq * (1.0f / HID) - mu * mu;
    float r   = rsqrtf(var + LN_EPS);

    float4 o4;
    o4.x = (v.x - mu) * r;
    o4.y = (v.y - mu) * r;
    o4.z = (v.z - mu) * r;
    o4.w = (v.w - mu) * r;
    ((float4*)(g_yA + (size_t)row * HID))[lane] = o4;
    store_h4(g_hA, row, lane, o4);
    ((float4*)(out + (size_t)row * HID))[lane] = v;
}

// ------------------------------ CSR build ----------------------------------
__global__ void k_count(const int* __restrict__ idx) {
    int e = blockIdx.x * blockDim.x + threadIdx.x;
    if (e < NEDGES) atomicAdd(&g_count[idx[e]], 1);
}

__device__ __forceinline__ int block_incl_scan(int v, int* ws) {
    int lane = threadIdx.x & 31, wid = threadIdx.x >> 5;
    int x = v;
    #pragma unroll
    for (int o = 1; o < 32; o <<= 1) {
        int t = __shfl_up_sync(0xFFFFFFFFu, x, o);
        if (lane >= o) x += t;
    }
    if (lane == 31) ws[wid] = x;
    __syncthreads();
    if (wid == 0) {
        int y = (lane < (blockDim.x >> 5)) ? ws[lane] : 0;
        #pragma unroll
        for (int o = 1; o < 32; o <<= 1) {
            int t = __shfl_up_sync(0xFFFFFFFFu, y, o);
            if (lane >= o) y += t;
        }
        ws[lane] = y;
    }
    __syncthreads();
    return x + (wid ? ws[wid - 1] : 0);
}

// Block-local scan + atomic base grab (CSR needs only disjoint slices).
__global__ void k_scan() {
    __shared__ int ws[32];
    __shared__ int s_base;
    int gid = blockIdx.x * SCAN_BLK + threadIdx.x;
    int v = (gid < NNODES) ? g_count[gid] : 0;
    int incl = block_incl_scan(v, ws);
    if (threadIdx.x == SCAN_BLK - 1) s_base = atomicAdd(&g_total, incl);
    __syncthreads();
    if (gid < NNODES) {
        int o = s_base + incl - v;
        g_off[gid]    = o;
        g_cursor[gid] = o;
    }
}

__global__ void k_scatter(const int* __restrict__ idx,
                          const int* __restrict__ ptype) {
    int e = blockIdx.x * blockDim.x + threadIdx.x;
    if (e >= NEDGES) return;
    int row = idx[e];
    int pos = atomicAdd(&g_cursor[row], 1);
    g_edge[pos] = make_int2(row, idx[NEDGES + e] | (ptype[e] << 19));
}

// ---------------------------------------------------------------------------
// Pre-pass: layer-independent eig dot per sorted edge, 2 edges per half-warp.
//   g_yeig[pos] = dot(eigs[row], eigs[col])      (EIG == 16 lanes)
__global__ void __launch_bounds__(256) k_prep(const float* __restrict__ eigs) {
    int tid  = blockIdx.x * blockDim.x + threadIdx.x;
    int h    = tid >> 4;
    int lane = threadIdx.x & 15;
    if (h >= NHALF) return;

    int2 ed0 = g_edge[2 * h];
    int2 ed1 = g_edge[2 * h + 1];

    float p0 = eigs[(size_t)ed0.x * EIG + lane] * eigs[(size_t)(ed0.y & 0x7FFFF) * EIG + lane];
    float p1 = eigs[(size_t)ed1.x * EIG + lane] * eigs[(size_t)(ed1.y & 0x7FFFF) * EIG + lane];
    #pragma unroll
    for (int o = 8; o; o >>= 1) {
        p0 += __shfl_xor_sync(0xFFFFFFFFu, p0, o);
        p1 += __shfl_xor_sync(0xFFFFFFFFu, p1, o);
    }
    if (lane == 0) ((float2*)g_yeig)[h] = make_float2(p0, p1);
}

// ---------------------------------------------------------------------------
// Edge-parallel score, 2 edges per half-warp (interleaved chains), fp16 y.
//   g_e0[pos] = exp(dot(y[r],y[c])/8 + exp(lam)*g_yeig[pos])
// (Softmax max-shift dropped: ratio shift-invariant, magnitudes f32-safe.)
__global__ void __launch_bounds__(256) k_score(const __half* __restrict__ hy,
                                               const float* __restrict__ lam_l) {
    int tid  = blockIdx.x * blockDim.x + threadIdx.x;
    int h    = tid >> 4;
    int lane = threadIdx.x & 15;
    if (h >= NHALF) return;

    int2 ed0 = g_edge[2 * h];
    int2 ed1 = g_edge[2 * h + 1];

    uint2 ur0 = ((const uint2*)(hy + (size_t)ed0.x * HID))[lane];
    uint2 uc0 = ((const uint2*)(hy + (size_t)(ed0.y & 0x7FFFF) * HID))[lane];
    uint2 ur1 = ((const uint2*)(hy + (size_t)ed1.x * HID))[lane];
    uint2 uc1 = ((const uint2*)(hy + (size_t)(ed1.y & 0x7FFFF) * HID))[lane];

    float p0 = hdot8(ur0, uc0);
    float p1 = hdot8(ur1, uc1);

    #pragma unroll
    for (int o = 8; o; o >>= 1) {
        p0 += __shfl_xor_sync(0xFFFFFFFFu, p0, o);
        p1 += __shfl_xor_sync(0xFFFFFFFFu, p1, o);
    }

    if (lane == 0) {
        float elam = __expf(lam_l[0]);
        float2 ye = ((const float2*)g_yeig)[h];
        float e00 = __expf(p0 * 0.125f + elam * ye.x);
        float e01 = __expf(p1 * 0.125f + elam * ye.y);
        ((float2*)g_e0)[h] = make_float2(e00, e01);
    }
}

// ---------------------------------------------------------------------------
// Row-parallel aggregation: WARP per row, lanes 0-15 take even edges and
// lanes 16-31 odd edges (same registers/thread as half-warp version, half
// the serial trip count). Combine halves with one shfl_xor(16) per value.
// Linearity: res = 0.5*(Σe0·y[c])/Σe0 + 0.5*(Σep·y[c])/Σep.
//   final==0 : out += res ; ydst/hdst = LN(res)
//   final==1 : out = (out + res) / 3
__global__ void __launch_bounds__(256) k_agg(const float* __restrict__ ysrc,
                                             float* __restrict__ ydst,
                                             __half* __restrict__ hdst,
                                             const float* __restrict__ pemb,
                                             float* __restrict__ out,
                                             int final_mode) {
    __shared__ float s_ep[NPATHS];
    if (threadIdx.x < NPATHS) s_ep[threadIdx.x] = __expf(pemb[threadIdx.x]);
    __syncthreads();

    int row  = (blockIdx.x * blockDim.x + threadIdx.x) >> 5;
    int half = (threadIdx.x >> 4) & 1;
    int lane = threadIdx.x & 15;
    if (row >= NNODES) return;

    int start = g_off[row];
    int end   = start + g_count[row];

    float4 acc0 = make_float4(0.f, 0.f, 0.f, 0.f);
    float4 acc1 = make_float4(0.f, 0.f, 0.f, 0.f);
    float  den0 = 0.0f, den1 = 0.0f;

    for (int pos = start + half; pos < end; pos += 2) {
        int   pk = g_edge[pos].y;              // broadcast within 16-group
        int   c  = pk & 0x7FFFF;
        float e0 = g_e0[pos];
        float ep = s_ep[pk >> 19];
        float4 yc = ((const float4*)(ysrc + (size_t)c * HID))[lane];
        den0 += e0;  den1 += ep;
        acc0.x += e0 * yc.x;  acc0.y += e0 * yc.y;
        acc0.z += e0 * yc.z;  acc0.w += e0 * yc.w;
        acc1.x += ep * yc.x;  acc1.y += ep * yc.y;
        acc1.z += ep * yc.z;  acc1.w += ep * yc.w;
    }

    // merge the two 16-lane halves (partner lane holds same feature slot)
    acc0.x += __shfl_xor_sync(0xFFFFFFFFu, acc0.x, 16);
    acc0.y += __shfl_xor_sync(0xFFFFFFFFu, acc0.y, 16);
    acc0.z += __shfl_xor_sync(0xFFFFFFFFu, acc0.z, 16);
    acc0.w += __shfl_xor_sync(0xFFFFFFFFu, acc0.w, 16);
    acc1.x += __shfl_xor_sync(0xFFFFFFFFu, acc1.x, 16);
    acc1.y += __shfl_xor_sync(0xFFFFFFFFu, acc1.y, 16);
    acc1.z += __shfl_xor_sync(0xFFFFFFFFu, acc1.z, 16);
    acc1.w += __shfl_xor_sync(0xFFFFFFFFu, acc1.w, 16);
    den0   += __shfl_xor_sync(0xFFFFFFFFu, den0, 16);
    den1   += __shfl_xor_sync(0xFFFFFFFFu, den1, 16);

    float4 res = make_float4(0.f, 0.f, 0.f, 0.f);
    if (end > start) {
        float i0 = 0.5f / den0;
        float i1 = 0.5f / den1;
        res.x = acc0.x * i0 + acc1.x * i1;
        res.y = acc0.y * i0 + acc1.y * i1;
        res.z = acc0.z * i0 + acc1.z * i1;
        res.w = acc0.w * i0 + acc1.w * i1;
    }

    float4* op = (float4*)(out + (size_t)row * HID);
    if (final_mode) {
        if (half == 0) {
            float4 cur = op[lane];
            cur.x = (cur.x + res.x) * (1.0f / 3.0f);
            cur.y = (cur.y + res.y) * (1.0f / 3.0f);
            cur.z = (cur.z + res.z) * (1.0f / 3.0f);
            cur.w = (cur.w + res.w) * (1.0f / 3.0f);
            op[lane] = cur;
        }
    } else {
        if (half == 0) {
            float4 cur = op[lane];
            cur.x += res.x; cur.y += res.y; cur.z += res.z; cur.w += res.w;
            op[lane] = cur;
        }

        // LN(res): both halves hold identical res; shuffles (offsets<16) stay
        // within each half, so all 32 lanes compute identical stats.
        float s  = res.x + res.y + res.z + res.w;
        float sq = res.x * res.x + res.y * res.y + res.z * res.z + res.w * res.w;
        #pragma unroll
        for (int o = 8; o; o >>= 1) {
            s  += __shfl_xor_sync(0xFFFFFFFFu, s,  o);
            sq += __shfl_xor_sync(0xFFFFFFFFu, sq, o);
        }
        float mu  = s * (1.0f / HID);
        float var = sq * (1.0f / HID) - mu * mu;
        float rr  = rsqrtf(var + LN_EPS);
        if (half == 0) {
            float4 o4;
            o4.x = (res.x - mu) * rr;
            o4.y = (res.y - mu) * rr;
            o4.z = (res.z - mu) * rr;
            o4.w = (res.w - mu) * rr;
            ((float4*)(ydst + (size_t)row * HID))[lane] = o4;
            store_h4(hdst, row, lane, o4);
        }
    }
}

// ---------------------------------------------------------------------------
extern "C" void kernel_launch(void* const* d_in, const int* in_sizes, int n_in,
                              void* d_out, int out_size) {
    const float* ue   = (const float*)d_in[0];
    const float* ie   = (const float*)d_in[1];
    const float* eigs = (const float*)d_in[2];
    const float* lam  = (const float*)d_in[3];
    const float* pw   = (const float*)d_in[4];
    const int*   idx  = (const int*)d_in[5];
    const int*   pt   = (const int*)d_in[6];
    float*       out  = (float*)d_out;

    float *yA, *yB;
    __half *hA, *hB;
    cudaGetSymbolAddress((void**)&yA, g_yA);
    cudaGetSymbolAddress((void**)&yB, g_yB);
    cudaGetSymbolAddress((void**)&hA, g_hA);
    cudaGetSymbolAddress((void**)&hB, g_hB);

    const int edge_grid = (NEDGES + 255) / 256;
    const int half_grid = ((NNODES * 16) + 255) / 256;   // half-warp per row
    const int warp_grid = ((NNODES * 32) + 255) / 256;   // warp per row (agg)
    const int pair_grid = ((NHALF * 16) + 255) / 256;    // half-warp per 2 edges

    // ln0 first (also zeroes CSR histogram), then CSR build + eig-dot prepass
    k_ln0    <<<half_grid, 256>>>(ue, ie, out);
    k_count  <<<edge_grid, 256>>>(idx);
    k_scan   <<<NBLK1, SCAN_BLK>>>();
    k_scatter<<<edge_grid, 256>>>(idx, pt);
    k_prep   <<<pair_grid, 256>>>(eigs);

    // layer 0: score(fp16 yA) -> agg(f32 yA) ; out += emb1, yB/hB = LN(emb1)
    k_score<<<pair_grid, 256>>>(hA, lam + 0);
    k_agg  <<<warp_grid, 256>>>(yA, yB, hB, pw + 0 * NPATHS, out, 0);

    // layer 1: score(fp16 yB) -> agg(f32 yB) -> out = (out + emb2)/3
    k_score<<<pair_grid, 256>>>(hB, lam + 1);
    k_agg  <<<warp_grid, 256>>>(yB, yA, hA, pw + 1 * NPATHS, out, 1);
}

// round 17
// speedup vs baseline: 1.8925x; 1.8925x over previous
#include <cuda_runtime.h>
#include <cuda_fp16.h>

#define NUSERS  100000
#define NNODES  300000
#define NEDGES  1250000
#define HID     64
#define EIG     16
#define NPATHS  14
#define LN_EPS  1e-5f

#define SCAN_BLK 1024
#define NBLK1    ((NNODES + SCAN_BLK - 1) / SCAN_BLK)   // 293
#define NHALF    (NEDGES / 2)                            // 625000 (even)

// ---------------- scratch (device globals: no allocation allowed) ----------
__device__ __half g_hA[(size_t)NNODES * HID];    // fp16 layernormed emb (L0)
__device__ __half g_hB[(size_t)NNODES * HID];    // fp16 layernormed emb (L1)
__device__ __align__(16) int2  g_edge[NEDGES];   // {row, col|pt<<19} sorted by row
__device__ __align__(16) float g_yeig[NEDGES];   // dot(eig[r],eig[c]) per edge
__device__ __align__(16) float g_e0[NEDGES];     // exp(s0) per sorted edge
__device__ int    g_count[NNODES];               // row degree
__device__ int    g_off[NNODES];                 // CSR row offsets
__device__ int    g_cursor[NNODES];              // scatter cursors
__device__ int    g_total;                       // scan base allocator

// ---------------------------------------------------------------------------
__device__ __forceinline__ void store_h4(__half* hbase, int row, int lane, float4 v) {
    union { uint2 u; __half2 h[2]; } pk;
    pk.h[0] = __floats2half2_rn(v.x, v.y);
    pk.h[1] = __floats2half2_rn(v.z, v.w);
    ((uint2*)(hbase + (size_t)row * HID))[lane] = pk.u;
}

__device__ __forceinline__ float4 h4_to_f4(uint2 u) {
    float2 a = __half22float2(*(const __half2*)&u.x);
    float2 b = __half22float2(*(const __half2*)&u.y);
    return make_float4(a.x, a.y, b.x, b.y);
}

__device__ __forceinline__ float hdot8(uint2 ur, uint2 uc) {
    float2 a = __half22float2(*(const __half2*)&ur.x);
    float2 b = __half22float2(*(const __half2*)&uc.x);
    float p = a.x * b.x + a.y * b.y;
    a = __half22float2(*(const __half2*)&ur.y);
    b = __half22float2(*(const __half2*)&uc.y);
    return p + a.x * b.x + a.y * b.y;
}

// ---------------------------------------------------------------------------
// Layer-0 layernorm: half-warp per row, float4 lanes. Runs FIRST; also zeroes
// the CSR histogram.  g_hA = LN(concat(ue,ie)); out = concat(ue,ie)
__global__ void __launch_bounds__(256) k_ln0(const float* __restrict__ ue,
                                             const float* __restrict__ ie,
                                             float* __restrict__ out) {
    int tid  = blockIdx.x * blockDim.x + threadIdx.x;
    int row  = tid >> 4;
    int lane = threadIdx.x & 15;
    if (row >= NNODES) return;

    if (lane == 0) g_count[row] = 0;
    if (tid == 0)  g_total = 0;

    const float* src = (row < NUSERS)
        ? ue + (size_t)row * HID
        : ie + (size_t)(row - NUSERS) * HID;
    float4 v = ((const float4*)src)[lane];

    float s  = v.x + v.y + v.z + v.w;
    float sq = v.x * v.x + v.y * v.y + v.z * v.z + v.w * v.w;
    #pragma unroll
    for (int o = 8; o; o >>= 1) {
        s  += __shfl_xor_sync(0xFFFFFFFFu, s,  o);
        sq += __shfl_xor_sync(0xFFFFFFFFu, sq, o);
    }
    float mu  = s * (1.0f / HID);
    float var = sq * (1.0f / HID) - mu * mu;
    float r   = rsqrtf(var + LN_EPS);

    float4 o4;
    o4.x = (v.x - mu) * r;
    o4.y = (v.y - mu) * r;
    o4.z = (v.z - mu) * r;
    o4.w = (v.w - mu) * r;
    store_h4(g_hA, row, lane, o4);
    ((float4*)(out + (size_t)row * HID))[lane] = v;
}

// ------------------------------ CSR build ----------------------------------
__global__ void k_count(const int* __restrict__ idx) {
    int e = blockIdx.x * blockDim.x + threadIdx.x;
    if (e < NEDGES) atomicAdd(&g_count[idx[e]], 1);
}

__device__ __forceinline__ int block_incl_scan(int v, int* ws) {
    int lane = threadIdx.x & 31, wid = threadIdx.x >> 5;
    int x = v;
    #pragma unroll
    for (int o = 1; o < 32; o <<= 1) {
        int t = __shfl_up_sync(0xFFFFFFFFu, x, o);
        if (lane >= o) x += t;
    }
    if (lane == 31) ws[wid] = x;
    __syncthreads();
    if (wid == 0) {
        int y = (lane < (blockDim.x >> 5)) ? ws[lane] : 0;
        #pragma unroll
        for (int o = 1; o < 32; o <<= 1) {
            int t = __shfl_up_sync(0xFFFFFFFFu, y, o);
            if (lane >= o) y += t;
        }
        ws[lane] = y;
    }
    __syncthreads();
    return x + (wid ? ws[wid - 1] : 0);
}

// Block-local scan + atomic base grab (CSR needs only disjoint slices).
__global__ void k_scan() {
    __shared__ int ws[32];
    __shared__ int s_base;
    int gid = blockIdx.x * SCAN_BLK + threadIdx.x;
    int v = (gid < NNODES) ? g_count[gid] : 0;
    int incl = block_incl_scan(v, ws);
    if (threadIdx.x == SCAN_BLK - 1) s_base = atomicAdd(&g_total, incl);
    __syncthreads();
    if (gid < NNODES) {
        int o = s_base + incl - v;
        g_off[gid]    = o;
        g_cursor[gid] = o;
    }
}

__global__ void k_scatter(const int* __restrict__ idx,
                          const int* __restrict__ ptype) {
    int e = blockIdx.x * blockDim.x + threadIdx.x;
    if (e >= NEDGES) return;
    int row = idx[e];
    int pos = atomicAdd(&g_cursor[row], 1);
    g_edge[pos] = make_int2(row, idx[NEDGES + e] | (ptype[e] << 19));
}

// ---------------------------------------------------------------------------
// Pre-pass: layer-independent eig dot per sorted edge, 2 edges per half-warp.
//   g_yeig[pos] = dot(eigs[row], eigs[col])      (EIG == 16 lanes)
__global__ void __launch_bounds__(256) k_prep(const float* __restrict__ eigs) {
    int tid  = blockIdx.x * blockDim.x + threadIdx.x;
    int h    = tid >> 4;
    int lane = threadIdx.x & 15;
    if (h >= NHALF) return;

    int2 ed0 = g_edge[2 * h];
    int2 ed1 = g_edge[2 * h + 1];

    float p0 = eigs[(size_t)ed0.x * EIG + lane] * eigs[(size_t)(ed0.y & 0x7FFFF) * EIG + lane];
    float p1 = eigs[(size_t)ed1.x * EIG + lane] * eigs[(size_t)(ed1.y & 0x7FFFF) * EIG + lane];
    #pragma unroll
    for (int o = 8; o; o >>= 1) {
        p0 += __shfl_xor_sync(0xFFFFFFFFu, p0, o);
        p1 += __shfl_xor_sync(0xFFFFFFFFu, p1, o);
    }
    if (lane == 0) ((float2*)g_yeig)[h] = make_float2(p0, p1);
}

// ---------------------------------------------------------------------------
// Edge-parallel score, 2 edges per half-warp (interleaved chains), fp16 y.
//   g_e0[pos] = exp(dot(y[r],y[c])/8 + exp(lam)*g_yeig[pos])
// (Softmax max-shift dropped: ratio shift-invariant, magnitudes f32-safe.)
__global__ void __launch_bounds__(256) k_score(const __half* __restrict__ hy,
                                               const float* __restrict__ lam_l) {
    int tid  = blockIdx.x * blockDim.x + threadIdx.x;
    int h    = tid >> 4;
    int lane = threadIdx.x & 15;
    if (h >= NHALF) return;

    int2 ed0 = g_edge[2 * h];
    int2 ed1 = g_edge[2 * h + 1];

    uint2 ur0 = ((const uint2*)(hy + (size_t)ed0.x * HID))[lane];
    uint2 uc0 = ((const uint2*)(hy + (size_t)(ed0.y & 0x7FFFF) * HID))[lane];
    uint2 ur1 = ((const uint2*)(hy + (size_t)ed1.x * HID))[lane];
    uint2 uc1 = ((const uint2*)(hy + (size_t)(ed1.y & 0x7FFFF) * HID))[lane];

    float p0 = hdot8(ur0, uc0);
    float p1 = hdot8(ur1, uc1);

    #pragma unroll
    for (int o = 8; o; o >>= 1) {
        p0 += __shfl_xor_sync(0xFFFFFFFFu, p0, o);
        p1 += __shfl_xor_sync(0xFFFFFFFFu, p1, o);
    }

    if (lane == 0) {
        float elam = __expf(lam_l[0]);
        float2 ye = ((const float2*)g_yeig)[h];
        float e00 = __expf(p0 * 0.125f + elam * ye.x);
        float e01 = __expf(p1 * 0.125f + elam * ye.y);
        ((float2*)g_e0)[h] = make_float2(e00, e01);
    }
}

// ---------------------------------------------------------------------------
// Row-parallel aggregation, half-warp per row, fp16 y[c] gather (f32 accum).
// Linearity: res = 0.5*(Σe0·y[c])/Σe0 + 0.5*(Σep·y[c])/Σep.
//   final==0 : out += res ; hdst = LN(res)  (next layer's y)
//   final==1 : out = (out + res) / 3
__global__ void __launch_bounds__(256) k_agg(const __half* __restrict__ hsrc,
                                             __half* __restrict__ hdst,
                                             const float* __restrict__ pemb,
                                             float* __restrict__ out,
                                             int final_mode) {
    __shared__ float s_ep[NPATHS];
    if (threadIdx.x < NPATHS) s_ep[threadIdx.x] = __expf(pemb[threadIdx.x]);
    __syncthreads();

    int tid  = blockIdx.x * blockDim.x + threadIdx.x;
    int row  = tid >> 4;
    int lane = threadIdx.x & 15;
    if (row >= NNODES) return;

    int start = g_off[row];
    int end   = start + g_count[row];

    float4 acc0 = make_float4(0.f, 0.f, 0.f, 0.f);
    float4 acc1 = make_float4(0.f, 0.f, 0.f, 0.f);
    float  den0 = 0.0f, den1 = 0.0f;

    #pragma unroll 4
    for (int pos = start; pos < end; ++pos) {
        int   pk = g_edge[pos].y;              // broadcast
        int   c  = pk & 0x7FFFF;
        float e0 = g_e0[pos];                  // broadcast
        float ep = s_ep[pk >> 19];
        float4 yc = h4_to_f4(((const uint2*)(hsrc + (size_t)c * HID))[lane]);
        den0 += e0;  den1 += ep;
        acc0.x += e0 * yc.x;  acc0.y += e0 * yc.y;
        acc0.z += e0 * yc.z;  acc0.w += e0 * yc.w;
        acc1.x += ep * yc.x;  acc1.y += ep * yc.y;
        acc1.z += ep * yc.z;  acc1.w += ep * yc.w;
    }

    float4 res = make_float4(0.f, 0.f, 0.f, 0.f);
    if (end > start) {
        float i0 = 0.5f / den0;
        float i1 = 0.5f / den1;
        res.x = acc0.x * i0 + acc1.x * i1;
        res.y = acc0.y * i0 + acc1.y * i1;
        res.z = acc0.z * i0 + acc1.z * i1;
        res.w = acc0.w * i0 + acc1.w * i1;
    }

    float4* op = (float4*)(out + (size_t)row * HID);
    if (final_mode) {
        float4 cur = op[lane];
        cur.x = (cur.x + res.x) * (1.0f / 3.0f);
        cur.y = (cur.y + res.y) * (1.0f / 3.0f);
        cur.z = (cur.z + res.z) * (1.0f / 3.0f);
        cur.w = (cur.w + res.w) * (1.0f / 3.0f);
        op[lane] = cur;
    } else {
        float4 cur = op[lane];
        cur.x += res.x; cur.y += res.y; cur.z += res.z; cur.w += res.w;
        op[lane] = cur;

        // LN(res) -> hdst for next layer (epilogue only)
        float s  = res.x + res.y + res.z + res.w;
        float sq = res.x * res.x + res.y * res.y + res.z * res.z + res.w * res.w;
        #pragma unroll
        for (int o = 8; o; o >>= 1) {
            s  += __shfl_xor_sync(0xFFFFFFFFu, s,  o);
            sq += __shfl_xor_sync(0xFFFFFFFFu, sq, o);
        }
        float mu  = s * (1.0f / HID);
        float var = sq * (1.0f / HID) - mu * mu;
        float rr  = rsqrtf(var + LN_EPS);
        float4 o4;
        o4.x = (res.x - mu) * rr;
        o4.y = (res.y - mu) * rr;
        o4.z = (res.z - mu) * rr;
        o4.w = (res.w - mu) * rr;
        store_h4(hdst, row, lane, o4);
    }
}

// ---------------------------------------------------------------------------
extern "C" void kernel_launch(void* const* d_in, const int* in_sizes, int n_in,
                              void* d_out, int out_size) {
    const float* ue   = (const float*)d_in[0];
    const float* ie   = (const float*)d_in[1];
    const float* eigs = (const float*)d_in[2];
    const float* lam  = (const float*)d_in[3];
    const float* pw   = (const float*)d_in[4];
    const int*   idx  = (const int*)d_in[5];
    const int*   pt   = (const int*)d_in[6];
    float*       out  = (float*)d_out;

    __half *hA, *hB;
    cudaGetSymbolAddress((void**)&hA, g_hA);
    cudaGetSymbolAddress((void**)&hB, g_hB);

    const int edge_grid = (NEDGES + 255) / 256;
    const int half_grid = ((NNODES * 16) + 255) / 256;   // half-warp per row
    const int pair_grid = ((NHALF * 16) + 255) / 256;    // half-warp per 2 edges

    // ln0 first (also zeroes CSR histogram), then CSR build + eig-dot prepass
    k_ln0    <<<half_grid, 256>>>(ue, ie, out);
    k_count  <<<edge_grid, 256>>>(idx);
    k_scan   <<<NBLK1, SCAN_BLK>>>();
    k_scatter<<<edge_grid, 256>>>(idx, pt);
    k_prep   <<<pair_grid, 256>>>(eigs);

    // layer 0: score(hA) -> agg(hA) ; out += emb1, hB = LN(emb1)
    k_score<<<pair_grid, 256>>>(hA, lam + 0);
    k_agg  <<<half_grid, 256>>>(hA, hB, pw + 0 * NPATHS, out, 0);

    // layer 1: score(hB) -> agg(hB) -> out = (out + emb2)/3
    k_score<<<pair_grid, 256>>>(hB, lam + 1);
    k_agg  <<<half_grid, 256>>>(hB, hA, pw + 1 * NPATHS, out, 1);
}